// round 1
// baseline (speedup 1.0000x reference)
#include <cuda_runtime.h>
#include <math.h>

// ---------------------------------------------------------------------------
// Problem constants
// ---------------------------------------------------------------------------
#define T_DATA 20000
#define E_NO   1000
#define I_NO   200
#define T_NO   200
#define SUB    20
#define HN     10
#define COSN   20

#define OFF_V      0
#define N_V        (T_DATA)
#define OFF_CONVK  (OFF_V + N_V)                 // 20000
#define N_CONVK    (HN*SUB*2*T_NO)               // 80000
#define OFF_HIST   (OFF_CONVK + N_CONVK)         // 100000
#define N_HIST     (SUB*T_NO)                    // 4000
#define OFF_SPK    (OFF_HIST + N_HIST)           // 104000
#define N_SPK      (T_DATA*SUB)                  // 400000
#define OFF_TH     (OFF_SPK + N_SPK)             // 504000

#define PI_F 3.14159274101257324f

// ---------------------------------------------------------------------------
// Device scratch (no allocations allowed)
// ---------------------------------------------------------------------------
__device__ float g_basis[COSN * T_NO];            // [b][t]
__device__ float g_CK[SUB * T_NO * 2 * HN];       // [s][u][i*10+h]
__device__ float g_w[SUB * 256];                  // scan weights, zero padded: w[s][d]=hist_kern[s][200-d], d=1..200
__device__ float g_K[SUB * T_NO];                 // root alpha kernel (lag-indexed)
__device__ float g_SgT[2 * SUB * T_DATA];         // [channel][t], channel 2s=e, 2s+1=i
__device__ float g_drive[SUB * T_DATA];           // [s][t]

// ---------------------------------------------------------------------------
// Kernel 0: raised-cosine basis
// ---------------------------------------------------------------------------
__global__ void basis_kernel() {
    int idx = blockIdx.x * blockDim.x + threadIdx.x;
    if (idx >= COSN * T_NO) return;
    int b = idx / T_NO;
    int t = idx % T_NO;
    float raw = 5.0f * logf((float)t + 1.0f);
    float phi = 1.57079632679f * (float)b;
    float d = raw - phi;
    float v = 0.0f;
    if (d >= -PI_F && d <= PI_F) v = 0.5f * cosf(d) + 0.5f;
    g_basis[idx] = v;
}

// ---------------------------------------------------------------------------
// Kernel 1: prep — conv kernels, hist kernel, scan weights, root kernel
// ---------------------------------------------------------------------------
__global__ void prep_kernel(const float* __restrict__ Wconv,
                            const float* __restrict__ Whist,
                            const float* __restrict__ Tau,
                            const float* __restrict__ Wroot,
                            float* __restrict__ out) {
    int idx = blockIdx.x * blockDim.x + threadIdx.x;
    if (idx < 80000) {
        // conv_kern: o in [0,200), i in {0,1}, u in [0,200)
        int o = idx / 400;
        int i = (idx / 200) % 2;
        int u = idx % 200;
        float v = 0.0f;
        #pragma unroll
        for (int b = 0; b < COSN; b++)
            v = fmaf(Wconv[(o * 2 + i) * COSN + b], g_basis[b * T_NO + u], v);
        // output: flipped along time
        out[OFF_CONVK + o * 400 + i * 200 + (T_NO - 1 - u)] = v;
        // internal: lag-indexed (unflipped)
        int s = o / HN, h = o % HN;
        g_CK[s * (T_NO * 2 * HN) + u * (2 * HN) + i * HN + h] = v;
    } else if (idx < 84000) {
        int r = idx - 80000;
        int s = r / T_NO;
        int t = r % T_NO;
        float v = 0.0f;
        #pragma unroll
        for (int b = 0; b < COSN; b++)
            v = fmaf(Whist[s * COSN + b], g_basis[b * T_NO + t], v);
        out[OFF_HIST + r] = v;
    } else if (idx < 89120) {
        int r = idx - 84000;
        int s = r / 256;
        int d = r % 256;
        float v = 0.0f;
        if (d >= 1 && d <= T_NO) {
            int t = T_NO - d;
            #pragma unroll
            for (int b = 0; b < COSN; b++)
                v = fmaf(Whist[s * COSN + b], g_basis[b * T_NO + t], v);
        }
        g_w[s * 256 + d] = v;
    } else if (idx < 93120) {
        int r = idx - 89120;
        int s = r / T_NO;
        int u = r % T_NO;
        float E = expf(Tau[s]);
        float x = (float)u / E;
        g_K[s * T_NO + u] = x * expf(-x) * expf(Wroot[s]);
    }
}

// ---------------------------------------------------------------------------
// Kernel 2: grouping GEMM  Sg[c][t]  (c interleaved e/i per subunit)
// ---------------------------------------------------------------------------
__global__ void gemm_group_kernel(const float* __restrict__ Se,
                                  const float* __restrict__ Si,
                                  const float* __restrict__ Ce,
                                  const float* __restrict__ Ci) {
    __shared__ float sS[64][33];
    __shared__ float sC[20][33];
    int t0 = blockIdx.x * 64;
    int tid = threadIdx.x;
    int row = tid >> 2;      // 0..63
    int g   = tid & 3;       // 0..3
    float acce[5] = {0.f, 0.f, 0.f, 0.f, 0.f};
    float acci[5] = {0.f, 0.f, 0.f, 0.f, 0.f};

    // ---- excitatory: K = 1000
    for (int k0 = 0; k0 < E_NO; k0 += 32) {
        #pragma unroll
        for (int r = 0; r < 8; r++) {
            int idx = tid + 256 * r;
            int rl = idx >> 5, cl = idx & 31;
            int gt = t0 + rl, gk = k0 + cl;
            sS[rl][cl] = (gt < T_DATA && gk < E_NO) ? Se[gt * E_NO + gk] : 0.f;
        }
        #pragma unroll
        for (int r = 0; r < 3; r++) {
            int idx = tid + 256 * r;
            if (idx < 640) {
                int sl = idx >> 5, cl = idx & 31;
                int gk = k0 + cl;
                sC[sl][cl] = (gk < E_NO) ? Ce[sl * E_NO + gk] : 0.f;
            }
        }
        __syncthreads();
        #pragma unroll
        for (int kk = 0; kk < 32; kk++) {
            float a = sS[row][kk];
            #pragma unroll
            for (int j = 0; j < 5; j++)
                acce[j] = fmaf(a, sC[g + 4 * j][kk], acce[j]);
        }
        __syncthreads();
    }
    // ---- inhibitory: K = 200
    for (int k0 = 0; k0 < I_NO; k0 += 32) {
        #pragma unroll
        for (int r = 0; r < 8; r++) {
            int idx = tid + 256 * r;
            int rl = idx >> 5, cl = idx & 31;
            int gt = t0 + rl, gk = k0 + cl;
            sS[rl][cl] = (gt < T_DATA && gk < I_NO) ? Si[gt * I_NO + gk] : 0.f;
        }
        #pragma unroll
        for (int r = 0; r < 3; r++) {
            int idx = tid + 256 * r;
            if (idx < 640) {
                int sl = idx >> 5, cl = idx & 31;
                int gk = k0 + cl;
                sC[sl][cl] = (gk < I_NO) ? Ci[sl * I_NO + gk] : 0.f;
            }
        }
        __syncthreads();
        #pragma unroll
        for (int kk = 0; kk < 32; kk++) {
            float a = sS[row][kk];
            #pragma unroll
            for (int j = 0; j < 5; j++)
                acci[j] = fmaf(a, sC[g + 4 * j][kk], acci[j]);
        }
        __syncthreads();
    }
    int gt = t0 + row;
    if (gt < T_DATA) {
        #pragma unroll
        for (int j = 0; j < 5; j++) {
            int s = g + 4 * j;
            g_SgT[(2 * s) * T_DATA + gt]     = acce[j];
            g_SgT[(2 * s + 1) * T_DATA + gt] = acci[j];
        }
    }
}

// ---------------------------------------------------------------------------
// Kernel 3: 200-tap causal conv + leaky + FF net -> drive[s][t]
// ---------------------------------------------------------------------------
__global__ void conv_drive_kernel(const float* __restrict__ Wff,
                                  const float* __restrict__ Wff2,
                                  const float* __restrict__ thr) {
    int s  = blockIdx.y;
    int t0 = blockIdx.x * 128;
    int lt = threadIdx.x;

    __shared__ float sCK[T_NO * 2 * HN];   // 4000 floats, [u][i*10+h]
    __shared__ float sSe[328], sSi[328];
    __shared__ float sW[100], sW2[10];
    __shared__ float sth;

    for (int i = lt; i < 4000; i += 128)
        sCK[i] = g_CK[s * 4000 + i];
    for (int m = lt; m < 327; m += 128) {
        int gt = t0 - 199 + m;
        float ve = 0.f, vi = 0.f;
        if (gt >= 0 && gt < T_DATA) {
            ve = g_SgT[(2 * s) * T_DATA + gt];
            vi = g_SgT[(2 * s + 1) * T_DATA + gt];
        }
        sSe[m] = ve; sSi[m] = vi;
    }
    if (lt < 100) sW[lt]  = Wff[s * 100 + lt];
    if (lt < 10)  sW2[lt] = Wff2[s * 10 + lt];
    if (lt == 0)  sth = thr[s];
    __syncthreads();

    int t = t0 + lt;
    if (t >= T_DATA) return;

    float acc[10];
    #pragma unroll
    for (int h = 0; h < 10; h++) acc[h] = 0.f;

    #pragma unroll 2
    for (int u = 0; u < T_NO; u++) {
        float se = sSe[lt + 199 - u];
        float si = sSi[lt + 199 - u];
        const float4* c4 = reinterpret_cast<const float4*>(sCK + u * 20);
        float4 a0 = c4[0], a1 = c4[1], a2 = c4[2], a3 = c4[3], a4 = c4[4];
        acc[0] = fmaf(a0.x, se, fmaf(a2.z, si, acc[0]));
        acc[1] = fmaf(a0.y, se, fmaf(a2.w, si, acc[1]));
        acc[2] = fmaf(a0.z, se, fmaf(a3.x, si, acc[2]));
        acc[3] = fmaf(a0.w, se, fmaf(a3.y, si, acc[3]));
        acc[4] = fmaf(a1.x, se, fmaf(a3.z, si, acc[4]));
        acc[5] = fmaf(a1.y, se, fmaf(a3.w, si, acc[5]));
        acc[6] = fmaf(a1.z, se, fmaf(a4.x, si, acc[6]));
        acc[7] = fmaf(a1.w, se, fmaf(a4.y, si, acc[7]));
        acc[8] = fmaf(a2.x, se, fmaf(a4.z, si, acc[8]));
        acc[9] = fmaf(a2.y, se, fmaf(a4.w, si, acc[9]));
    }
    float co[10];
    #pragma unroll
    for (int h = 0; h < 10; h++)
        co[h] = acc[h] > 0.f ? acc[h] : 0.01f * acc[h];

    float dsum = 0.f;
    #pragma unroll
    for (int k = 0; k < 10; k++) {
        float v = 0.f;
        #pragma unroll
        for (int h = 0; h < 10; h++)
            v = fmaf(co[h], sW[h * 10 + k], v);
        v = v > 0.f ? v : 0.01f * v;
        dsum = fmaf(v, sW2[k], dsum);
    }
    g_drive[s * T_DATA + t] = dsum + sth;
}

// ---------------------------------------------------------------------------
// Kernel 4: sequential spike scan — one warp per subunit, 32-step chunks,
// replicated in-register triangular resolution.
// ---------------------------------------------------------------------------
__global__ void scan_kernel(float* __restrict__ out) {
    int s = blockIdx.x;
    int lane = threadIdx.x;

    __shared__ __align__(16) float ring[256];
    __shared__ float wext[256];
    for (int i = lane; i < 256; i += 32) {
        ring[i] = 0.f;
        wext[i] = g_w[s * 256 + i];
    }
    float wr[32];
    #pragma unroll
    for (int d = 0; d < 32; d++) wr[d] = g_w[s * 256 + d];  // wr[0] unused
    __syncwarp();

    const float* dr = g_drive + s * T_DATA;
    float* osp = out + OFF_SPK;
    float* oth = out + OFF_TH;

    for (int c = 0; c < T_DATA / 32; c++) {
        int t0 = c * 32;
        float b0 = dr[t0 + lane];
        float b1 = 0.f, b2 = 0.f, b3 = 0.f;
        // gather: lags from spikes of earlier chunks (ring), zero-padded weights
        #pragma unroll 2
        for (int c4 = 1; c4 <= 197; c4 += 4) {
            int p = (t0 - c4 - 3) & 255;
            float4 r4 = *reinterpret_cast<const float4*>(ring + p);
            b0 = fmaf(wext[c4 + lane],     r4.w, b0);
            b1 = fmaf(wext[c4 + 1 + lane], r4.z, b1);
            b2 = fmaf(wext[c4 + 2 + lane], r4.y, b2);
            b3 = fmaf(wext[c4 + 3 + lane], r4.x, b3);
        }
        float base = (b0 + b1) + (b2 + b3);

        // broadcast all 32 base values to every lane
        float v[32];
        #pragma unroll
        for (int k = 0; k < 32; k++)
            v[k] = __shfl_sync(0xffffffffu, base, k);

        // replicated serial resolution (static register indices)
        float myval = 0.f, myspk = 0.f;
        #pragma unroll
        for (int j2 = 0; j2 < 32; j2++) {
            float spk = v[j2] > 0.f ? 1.f : 0.f;
            if (lane == j2) { myval = v[j2]; myspk = spk; }
            #pragma unroll
            for (int j = j2 + 1; j < 32; j++)
                v[j] = fmaf(spk, wr[j - j2], v[j]);
        }

        ring[(t0 + lane) & 255] = myspk;
        __syncwarp();

        oth[(t0 + lane) * SUB + s] = myval;
        osp[(t0 + lane) * SUB + s] = myspk;
    }
}

// ---------------------------------------------------------------------------
// Kernel 5: root alpha-kernel conv over spikes -> V[t]
// ---------------------------------------------------------------------------
__global__ void root_kernel(const float* __restrict__ spikes,
                            float* __restrict__ V) {
    int t0 = blockIdx.x * 128;
    int lt = threadIdx.x;

    __shared__ float sK[SUB * T_NO];       // 4000
    __shared__ float sSpk[SUB * 328];

    for (int i = lt; i < SUB * T_NO; i += 128) sK[i] = g_K[i];
    for (int i = lt; i < SUB * 327; i += 128) {
        int s = i / 327;
        int m = i % 327;
        int gt = t0 - 200 + m;
        sSpk[s * 328 + m] = (gt >= 0 && gt < T_DATA) ? spikes[gt * SUB + s] : 0.f;
    }
    __syncthreads();

    int t = t0 + lt;
    if (t >= T_DATA) return;

    float acc0 = 0.f, acc1 = 0.f;
    for (int s = 0; s < SUB; s++) {
        const float* Ks = sK + s * T_NO;
        const float* Ss = sSpk + s * 328 + lt;   // index m = lt + 199 - u
        #pragma unroll 4
        for (int u = 0; u < T_NO; u += 2) {
            acc0 = fmaf(Ks[u],     Ss[199 - u], acc0);
            acc1 = fmaf(Ks[u + 1], Ss[198 - u], acc1);
        }
    }
    V[t] = acc0 + acc1;
}

// ---------------------------------------------------------------------------
// Launch
// ---------------------------------------------------------------------------
extern "C" void kernel_launch(void* const* d_in, const int* in_sizes, int n_in,
                              void* d_out, int out_size) {
    const float* S_e    = (const float*)d_in[0];
    const float* S_i    = (const float*)d_in[1];
    const float* Csyn_e = (const float*)d_in[2];
    const float* Csyn_i = (const float*)d_in[3];
    const float* W_conv = (const float*)d_in[4];
    const float* thresh = (const float*)d_in[5];
    const float* W_ff   = (const float*)d_in[6];
    const float* W_ff2  = (const float*)d_in[7];
    const float* Tau    = (const float*)d_in[8];
    const float* W_root = (const float*)d_in[9];
    const float* W_hist = (const float*)d_in[10];
    float* out = (float*)d_out;

    (void)in_sizes; (void)n_in; (void)out_size;

    basis_kernel<<<(COSN * T_NO + 255) / 256, 256>>>();
    prep_kernel<<<(93120 + 255) / 256, 256>>>(W_conv, W_hist, Tau, W_root, out);
    gemm_group_kernel<<<(T_DATA + 63) / 64, 256>>>(S_e, S_i, Csyn_e, Csyn_i);
    {
        dim3 grid((T_DATA + 127) / 128, SUB);
        conv_drive_kernel<<<grid, 128>>>(W_ff, W_ff2, thresh);
    }
    scan_kernel<<<SUB, 32>>>(out);
    root_kernel<<<(T_DATA + 127) / 128, 128>>>(out + OFF_SPK, out + OFF_V);
}

// round 2
// speedup vs baseline: 2.6719x; 2.6719x over previous
#include <cuda_runtime.h>
#include <math.h>

// ---------------------------------------------------------------------------
// Problem constants
// ---------------------------------------------------------------------------
#define T_DATA 20000
#define E_NO   1000
#define I_NO   200
#define T_NO   200
#define SUB    20
#define HN     10
#define COSN   20
#define NCHUNK (T_DATA / 32)     // 625

#define OFF_V      0
#define OFF_CONVK  (T_DATA)                      // 20000
#define OFF_HIST   (OFF_CONVK + HN*SUB*2*T_NO)   // 100000
#define OFF_SPK    (OFF_HIST + SUB*T_NO)         // 104000
#define OFF_TH     (OFF_SPK + T_DATA*SUB)        // 504000

#define PI_F 3.14159274101257324f

// ---------------------------------------------------------------------------
// Device scratch (no allocations allowed)
// ---------------------------------------------------------------------------
__device__ float g_basis[COSN * T_NO];
__device__ float g_CK[SUB * T_NO * 2 * HN];       // [s][u][i*10+h]
__device__ float g_w[SUB * 256];                  // w[s][d]=hist_kern[s][200-d], d=1..200, else 0
__device__ float g_K[SUB * T_NO];                 // root alpha kernel (lag-indexed)
__device__ float g_SgT[2 * SUB * T_DATA];         // [channel][t]
__device__ float g_drive[SUB * T_DATA];           // [s][t]
__device__ float g_spk_sT[SUB * T_DATA];          // [s][t] spikes
__device__ float g_th_sT[SUB * T_DATA];           // [s][t] sub_thresh

// ---------------------------------------------------------------------------
// Kernel 0: raised-cosine basis
// ---------------------------------------------------------------------------
__global__ void basis_kernel() {
    int idx = blockIdx.x * blockDim.x + threadIdx.x;
    if (idx >= COSN * T_NO) return;
    int b = idx / T_NO;
    int t = idx % T_NO;
    float raw = 5.0f * logf((float)t + 1.0f);
    float phi = 1.57079632679f * (float)b;
    float d = raw - phi;
    float v = 0.0f;
    if (d >= -PI_F && d <= PI_F) v = 0.5f * cosf(d) + 0.5f;
    g_basis[idx] = v;
}

// ---------------------------------------------------------------------------
// Kernel 1: prep — conv kernels, hist kernel, scan weights, root kernel
// ---------------------------------------------------------------------------
__global__ void prep_kernel(const float* __restrict__ Wconv,
                            const float* __restrict__ Whist,
                            const float* __restrict__ Tau,
                            const float* __restrict__ Wroot,
                            float* __restrict__ out) {
    int idx = blockIdx.x * blockDim.x + threadIdx.x;
    if (idx < 80000) {
        int o = idx / 400;
        int i = (idx / 200) % 2;
        int u = idx % 200;
        float v = 0.0f;
        #pragma unroll
        for (int b = 0; b < COSN; b++)
            v = fmaf(Wconv[(o * 2 + i) * COSN + b], g_basis[b * T_NO + u], v);
        out[OFF_CONVK + o * 400 + i * 200 + (T_NO - 1 - u)] = v;
        int s = o / HN, h = o % HN;
        g_CK[s * (T_NO * 2 * HN) + u * (2 * HN) + i * HN + h] = v;
    } else if (idx < 84000) {
        int r = idx - 80000;
        int s = r / T_NO;
        int t = r % T_NO;
        float v = 0.0f;
        #pragma unroll
        for (int b = 0; b < COSN; b++)
            v = fmaf(Whist[s * COSN + b], g_basis[b * T_NO + t], v);
        out[OFF_HIST + r] = v;
    } else if (idx < 89120) {
        int r = idx - 84000;
        int s = r / 256;
        int d = r % 256;
        float v = 0.0f;
        if (d >= 1 && d <= T_NO) {
            int t = T_NO - d;
            #pragma unroll
            for (int b = 0; b < COSN; b++)
                v = fmaf(Whist[s * COSN + b], g_basis[b * T_NO + t], v);
        }
        g_w[s * 256 + d] = v;
    } else if (idx < 93120) {
        int r = idx - 89120;
        int s = r / T_NO;
        int u = r % T_NO;
        float E = expf(Tau[s]);
        float x = (float)u / E;
        g_K[s * T_NO + u] = x * expf(-x) * expf(Wroot[s]);
    }
}

// ---------------------------------------------------------------------------
// Kernel 2: grouping GEMM  Sg[c][t]
// ---------------------------------------------------------------------------
__global__ void gemm_group_kernel(const float* __restrict__ Se,
                                  const float* __restrict__ Si,
                                  const float* __restrict__ Ce,
                                  const float* __restrict__ Ci) {
    __shared__ float sS[64][33];
    __shared__ float sC[20][33];
    int t0 = blockIdx.x * 64;
    int tid = threadIdx.x;
    int row = tid >> 2;
    int g   = tid & 3;
    float acce[5] = {0.f, 0.f, 0.f, 0.f, 0.f};
    float acci[5] = {0.f, 0.f, 0.f, 0.f, 0.f};

    for (int k0 = 0; k0 < E_NO; k0 += 32) {
        #pragma unroll
        for (int r = 0; r < 8; r++) {
            int idx = tid + 256 * r;
            int rl = idx >> 5, cl = idx & 31;
            int gt = t0 + rl, gk = k0 + cl;
            sS[rl][cl] = (gt < T_DATA && gk < E_NO) ? Se[gt * E_NO + gk] : 0.f;
        }
        #pragma unroll
        for (int r = 0; r < 3; r++) {
            int idx = tid + 256 * r;
            if (idx < 640) {
                int sl = idx >> 5, cl = idx & 31;
                int gk = k0 + cl;
                sC[sl][cl] = (gk < E_NO) ? Ce[sl * E_NO + gk] : 0.f;
            }
        }
        __syncthreads();
        #pragma unroll
        for (int kk = 0; kk < 32; kk++) {
            float a = sS[row][kk];
            #pragma unroll
            for (int j = 0; j < 5; j++)
                acce[j] = fmaf(a, sC[g + 4 * j][kk], acce[j]);
        }
        __syncthreads();
    }
    for (int k0 = 0; k0 < I_NO; k0 += 32) {
        #pragma unroll
        for (int r = 0; r < 8; r++) {
            int idx = tid + 256 * r;
            int rl = idx >> 5, cl = idx & 31;
            int gt = t0 + rl, gk = k0 + cl;
            sS[rl][cl] = (gt < T_DATA && gk < I_NO) ? Si[gt * I_NO + gk] : 0.f;
        }
        #pragma unroll
        for (int r = 0; r < 3; r++) {
            int idx = tid + 256 * r;
            if (idx < 640) {
                int sl = idx >> 5, cl = idx & 31;
                int gk = k0 + cl;
                sC[sl][cl] = (gk < I_NO) ? Ci[sl * I_NO + gk] : 0.f;
            }
        }
        __syncthreads();
        #pragma unroll
        for (int kk = 0; kk < 32; kk++) {
            float a = sS[row][kk];
            #pragma unroll
            for (int j = 0; j < 5; j++)
                acci[j] = fmaf(a, sC[g + 4 * j][kk], acci[j]);
        }
        __syncthreads();
    }
    int gt = t0 + row;
    if (gt < T_DATA) {
        #pragma unroll
        for (int j = 0; j < 5; j++) {
            int s = g + 4 * j;
            g_SgT[(2 * s) * T_DATA + gt]     = acce[j];
            g_SgT[(2 * s + 1) * T_DATA + gt] = acci[j];
        }
    }
}

// ---------------------------------------------------------------------------
// Kernel 3: 200-tap causal conv + leaky + FF net -> drive[s][t]
// 128 threads, each computes 2 timesteps (256 per block) to halve kernel LDS.
// ---------------------------------------------------------------------------
__global__ void conv_drive_kernel(const float* __restrict__ Wff,
                                  const float* __restrict__ Wff2,
                                  const float* __restrict__ thr) {
    int s  = blockIdx.y;
    int t0 = blockIdx.x * 256;
    int lt = threadIdx.x;

    __shared__ float sCK[T_NO * 2 * HN];   // 4000 floats
    __shared__ float sSe[456], sSi[456];
    __shared__ float sW[100], sW2[10];
    __shared__ float sth;

    for (int i = lt; i < 4000; i += 128)
        sCK[i] = g_CK[s * 4000 + i];
    for (int m = lt; m < 455; m += 128) {
        int gt = t0 - 199 + m;
        float ve = 0.f, vi = 0.f;
        if (gt >= 0 && gt < T_DATA) {
            ve = g_SgT[(2 * s) * T_DATA + gt];
            vi = g_SgT[(2 * s + 1) * T_DATA + gt];
        }
        sSe[m] = ve; sSi[m] = vi;
    }
    if (lt < 100) sW[lt]  = Wff[s * 100 + lt];
    if (lt < 10)  sW2[lt] = Wff2[s * 10 + lt];
    if (lt == 0)  sth = thr[s];
    __syncthreads();

    float accA[10], accB[10];
    #pragma unroll
    for (int h = 0; h < 10; h++) { accA[h] = 0.f; accB[h] = 0.f; }

    #pragma unroll 2
    for (int u = 0; u < T_NO; u++) {
        float seA = sSe[lt + 199 - u];
        float siA = sSi[lt + 199 - u];
        float seB = sSe[lt + 327 - u];
        float siB = sSi[lt + 327 - u];
        const float4* c4 = reinterpret_cast<const float4*>(sCK + u * 20);
        float4 a0 = c4[0], a1 = c4[1], a2 = c4[2], a3 = c4[3], a4 = c4[4];
        accA[0] = fmaf(a0.x, seA, fmaf(a2.z, siA, accA[0]));
        accA[1] = fmaf(a0.y, seA, fmaf(a2.w, siA, accA[1]));
        accA[2] = fmaf(a0.z, seA, fmaf(a3.x, siA, accA[2]));
        accA[3] = fmaf(a0.w, seA, fmaf(a3.y, siA, accA[3]));
        accA[4] = fmaf(a1.x, seA, fmaf(a3.z, siA, accA[4]));
        accA[5] = fmaf(a1.y, seA, fmaf(a3.w, siA, accA[5]));
        accA[6] = fmaf(a1.z, seA, fmaf(a4.x, siA, accA[6]));
        accA[7] = fmaf(a1.w, seA, fmaf(a4.y, siA, accA[7]));
        accA[8] = fmaf(a2.x, seA, fmaf(a4.z, siA, accA[8]));
        accA[9] = fmaf(a2.y, seA, fmaf(a4.w, siA, accA[9]));
        accB[0] = fmaf(a0.x, seB, fmaf(a2.z, siB, accB[0]));
        accB[1] = fmaf(a0.y, seB, fmaf(a2.w, siB, accB[1]));
        accB[2] = fmaf(a0.z, seB, fmaf(a3.x, siB, accB[2]));
        accB[3] = fmaf(a0.w, seB, fmaf(a3.y, siB, accB[3]));
        accB[4] = fmaf(a1.x, seB, fmaf(a3.z, siB, accB[4]));
        accB[5] = fmaf(a1.y, seB, fmaf(a3.w, siB, accB[5]));
        accB[6] = fmaf(a1.z, seB, fmaf(a4.x, siB, accB[6]));
        accB[7] = fmaf(a1.w, seB, fmaf(a4.y, siB, accB[7]));
        accB[8] = fmaf(a2.x, seB, fmaf(a4.z, siB, accB[8]));
        accB[9] = fmaf(a2.y, seB, fmaf(a4.w, siB, accB[9]));
    }

    #pragma unroll
    for (int half = 0; half < 2; half++) {
        int t = t0 + lt + 128 * half;
        if (t >= T_DATA) continue;
        float co[10];
        #pragma unroll
        for (int h = 0; h < 10; h++) {
            float a = half ? accB[h] : accA[h];
            co[h] = a > 0.f ? a : 0.01f * a;
        }
        float dsum = 0.f;
        #pragma unroll
        for (int k = 0; k < 10; k++) {
            float v = 0.f;
            #pragma unroll
            for (int h = 0; h < 10; h++)
                v = fmaf(co[h], sW[h * 10 + k], v);
            v = v > 0.f ? v : 0.01f * v;
            dsum = fmaf(v, sW2[k], dsum);
        }
        g_drive[s * T_DATA + t] = dsum + sth;
    }
}

// ---------------------------------------------------------------------------
// Kernel 4: pipelined spike scan.
// 3 warps per subunit: warps 0,2 gather long-lag base (taps lane+33..200)
// one chunk ahead; warp 1 adds short lags (register weights) + resolves the
// 32-step recurrence in 4 sub-blocks of 8 with zero-padded register-weight
// cross updates.
// ---------------------------------------------------------------------------
__global__ void __launch_bounds__(96, 1) scan_kernel() {
    int s = blockIdx.x;
    int tid = threadIdx.x;
    int wid = tid >> 5, lane = tid & 31;

    __shared__ __align__(16) float ring[256];
    __shared__ __align__(16) float wext[256];
    __shared__ float baseB[2][2][32];

    for (int i = tid; i < 256; i += 96) {
        ring[i] = 0.f;
        wext[i] = g_w[s * 256 + i];
    }
    __syncthreads();

    const float* dr = g_drive + s * T_DATA;
    float* osp = g_spk_sT + s * T_DATA;
    float* oth = g_th_sT + s * T_DATA;

    if (wid != 1) {
        // ---------------- gather warps ----------------
        int g = wid >> 1;                 // wid 0 -> 0, wid 2 -> 1
        int c4lo = 33 + g * 84;           // 33..113 / 117..197
        float drcur = (g == 0) ? dr[lane] : 0.f;
        for (int it = 0; it <= NCHUNK; it++) {
            if (it < NCHUNK) {
                int T = it * 32;
                float drnx = 0.f;
                if (g == 0 && it + 1 < NCHUNK) drnx = dr[(it + 1) * 32 + lane];
                float b0 = 0.f, b1 = 0.f, b2 = 0.f, b3 = 0.f;
                #pragma unroll
                for (int q = 0; q < 21; q++) {
                    int c4 = c4lo + 4 * q;
                    int p = (T - c4 - 3) & 255;
                    float4 r4 = *reinterpret_cast<const float4*>(ring + p);
                    b0 = fmaf(wext[c4 + lane],     r4.w, b0);
                    b1 = fmaf(wext[c4 + 1 + lane], r4.z, b1);
                    b2 = fmaf(wext[c4 + 2 + lane], r4.y, b2);
                    b3 = fmaf(wext[c4 + 3 + lane], r4.x, b3);
                }
                float sum = (b0 + b1) + (b2 + b3);
                if (g == 0) sum += drcur;
                baseB[it & 1][g][lane] = sum;
                drcur = drnx;
            }
            __syncthreads();
        }
    } else {
        // ---------------- resolve warp ----------------
        // register weights
        float wregB[33];                  // taps lane+1..lane+32 (prev chunk)
        #pragma unroll
        for (int j = 1; j <= 32; j++) wregB[j] = g_w[s * 256 + lane + j];
        float wregU[32];                  // zero-padded w[lane-31+k]
        #pragma unroll
        for (int k = 0; k < 32; k++) {
            int idx = lane - 31 + k;
            wregU[k] = (idx >= 1) ? g_w[s * 256 + idx] : 0.f;
        }
        float wr[8];
        #pragma unroll
        for (int j = 1; j < 8; j++) wr[j] = g_w[s * 256 + j];

        for (int it = 0; it <= NCHUNK; it++) {
            if (it >= 1) {
                int c = it - 1;
                int T = c * 32;
                float v = baseB[c & 1][0][lane] + baseB[c & 1][1][lane];
                // Part A: taps lane+1..lane+32 = spikes of previous chunk
                float a0 = 0.f, a1 = 0.f, a2 = 0.f, a3 = 0.f;
                #pragma unroll
                for (int q = 0; q < 8; q++) {
                    int p = (T - 32 + 4 * q) & 255;
                    float4 r4 = *reinterpret_cast<const float4*>(ring + p);
                    a0 = fmaf(wregB[32 - 4 * q], r4.x, a0);
                    a1 = fmaf(wregB[31 - 4 * q], r4.y, a1);
                    a2 = fmaf(wregB[30 - 4 * q], r4.z, a2);
                    a3 = fmaf(wregB[29 - 4 * q], r4.w, a3);
                }
                v += (a0 + a1) + (a2 + a3);

                // 4 sub-blocks of 8: replicated 8x8 triangle + register-weight
                // zero-padded cross update (bit-identical to triangle values)
                #pragma unroll
                for (int b = 0; b < 4; b++) {
                    float sv[8], spk[8];
                    #pragma unroll
                    for (int i = 0; i < 8; i++)
                        sv[i] = __shfl_sync(0xffffffffu, v, 8 * b + i);
                    #pragma unroll
                    for (int i = 0; i < 8; i++) {
                        spk[i] = sv[i] > 0.f ? 1.f : 0.f;
                        #pragma unroll
                        for (int j = i + 1; j < 8; j++)
                            sv[j] = fmaf(spk[i], wr[j - i], sv[j]);
                    }
                    #pragma unroll
                    for (int i = 0; i < 8; i++)
                        v = fmaf(spk[i], wregU[31 - 8 * b - i], v);
                }

                float myspk = v > 0.f ? 1.f : 0.f;
                ring[(T + lane) & 255] = myspk;
                oth[T + lane] = v;
                osp[T + lane] = myspk;
            }
            __syncthreads();
        }
    }
}

// ---------------------------------------------------------------------------
// Kernel 5: transpose [s][t] -> out [t][s] (spikes + thresh)
// ---------------------------------------------------------------------------
__global__ void transpose_kernel(float* __restrict__ out) {
    __shared__ float sh[SUB][257];
    int t0 = blockIdx.x * 256;
    int tid = threadIdx.x;
    const float* in = blockIdx.y ? g_th_sT : g_spk_sT;
    float* op = out + (blockIdx.y ? OFF_TH : OFF_SPK);

    int t = t0 + tid;
    if (t < T_DATA) {
        #pragma unroll
        for (int s = 0; s < SUB; s++)
            sh[s][tid] = in[s * T_DATA + t];
    }
    __syncthreads();
    for (int i = tid; i < SUB * 256; i += 256) {
        int tl = i / SUB, s = i % SUB;
        int tt = t0 + tl;
        if (tt < T_DATA) op[tt * SUB + s] = sh[s][tl];
    }
}

// ---------------------------------------------------------------------------
// Kernel 6: root alpha-kernel conv over spikes ([s][t] layout) -> V[t]
// ---------------------------------------------------------------------------
__global__ void root_kernel(float* __restrict__ V) {
    int t0 = blockIdx.x * 128;
    int lt = threadIdx.x;

    __shared__ float sK[SUB * T_NO];
    __shared__ float sSpk[SUB * 328];

    for (int i = lt; i < SUB * T_NO; i += 128) sK[i] = g_K[i];
    for (int i = lt; i < SUB * 327; i += 128) {
        int s = i / 327;
        int m = i % 327;
        int gt = t0 - 200 + m;
        sSpk[s * 328 + m] = (gt >= 0 && gt < T_DATA) ? g_spk_sT[s * T_DATA + gt] : 0.f;
    }
    __syncthreads();

    int t = t0 + lt;
    if (t >= T_DATA) return;

    float acc0 = 0.f, acc1 = 0.f;
    for (int s = 0; s < SUB; s++) {
        const float* Ks = sK + s * T_NO;
        const float* Ss = sSpk + s * 328 + lt;
        #pragma unroll 4
        for (int u = 0; u < T_NO; u += 2) {
            acc0 = fmaf(Ks[u],     Ss[199 - u], acc0);
            acc1 = fmaf(Ks[u + 1], Ss[198 - u], acc1);
        }
    }
    V[t] = acc0 + acc1;
}

// ---------------------------------------------------------------------------
// Launch
// ---------------------------------------------------------------------------
extern "C" void kernel_launch(void* const* d_in, const int* in_sizes, int n_in,
                              void* d_out, int out_size) {
    const float* S_e    = (const float*)d_in[0];
    const float* S_i    = (const float*)d_in[1];
    const float* Csyn_e = (const float*)d_in[2];
    const float* Csyn_i = (const float*)d_in[3];
    const float* W_conv = (const float*)d_in[4];
    const float* thresh = (const float*)d_in[5];
    const float* W_ff   = (const float*)d_in[6];
    const float* W_ff2  = (const float*)d_in[7];
    const float* Tau    = (const float*)d_in[8];
    const float* W_root = (const float*)d_in[9];
    const float* W_hist = (const float*)d_in[10];
    float* out = (float*)d_out;

    (void)in_sizes; (void)n_in; (void)out_size;

    basis_kernel<<<(COSN * T_NO + 255) / 256, 256>>>();
    prep_kernel<<<(93120 + 255) / 256, 256>>>(W_conv, W_hist, Tau, W_root, out);
    gemm_group_kernel<<<(T_DATA + 63) / 64, 256>>>(S_e, S_i, Csyn_e, Csyn_i);
    {
        dim3 grid((T_DATA + 255) / 256, SUB);
        conv_drive_kernel<<<grid, 128>>>(W_ff, W_ff2, thresh);
    }
    scan_kernel<<<SUB, 96>>>();
    {
        dim3 grid((T_DATA + 255) / 256, 2);
        transpose_kernel<<<grid, 256>>>(out);
    }
    root_kernel<<<(T_DATA + 127) / 128, 128>>>(out + OFF_V);
}